// round 14
// baseline (speedup 1.0000x reference)
#include <cuda_runtime.h>
#include <cuda_fp16.h>
#include <cstdint>
#include <math.h>

#define B_   2
#define L_   1024
#define HS_  2048
#define NH_  8
#define HD_  256
#define DV_  512
#define KD_  2048
#define VD_  4096
#define E_   3
#define TOK_ 2048
#define NV_  8
#define DVS_ 64
#define QKVG_ 12288    // merged row: q(2048) k(2048) v(4096) g(4096)

// ---------------- scratch (static device arrays; no allocation) ----------------
__device__ __align__(16) float g_xqkvg[TOK_*QKVG_];
__device__ __align__(16) float g_q [TOK_*KD_];
__device__ __align__(16) float g_v [TOK_*VD_];
__device__ __align__(16) float g_ke[E_*TOK_*KD_];
__device__ __align__(16) float g_betaA[TOK_*E_*NH_];
__device__ __align__(16) float g_aA  [TOK_*E_*NH_];
__device__ __align__(16) float g_dec [E_*B_*NH_*L_];
__device__ __align__(16) float g_bm  [E_*B_*NH_*L_];
__device__ __align__(16) float g_opre[TOK_*VD_];

// split-fp16 buffers: A-side layout [hi | lo], B-side layout [hi | hi]
__device__ __align__(16) __half g_X2    [TOK_*2*HS_];
__device__ __align__(16) __half g_Wqkvg2[QKVG_*2*HS_];
__device__ __align__(16) __half g_Wo2   [HS_*2*VD_];
__device__ __align__(16) __half g_of2   [TOK_*2*VD_];
__device__ __align__(16) __half g_k2    [NH_*TOK_*2*HD_];
__device__ __align__(16) __half g_Wek2  [E_*NH_*HD_*2*HD_];

// ======================= helpers =============================================
__device__ __forceinline__ void cp16(uint32_t dst, const void* src) {
    asm volatile("cp.async.cg.shared.global [%0], [%1], 16;" :: "r"(dst), "l"(src));
}
#define CP_COMMIT() asm volatile("cp.async.commit_group;" ::: "memory")
#define CP_WAIT(n)  asm volatile("cp.async.wait_group %0;" :: "n"(n) : "memory")

#define MMA16816(d, a0, a1, a2, a3, b0, b1) \
    asm volatile("mma.sync.aligned.m16n8k16.row.col.f32.f16.f16.f32 " \
                 "{%0,%1,%2,%3}, {%4,%5,%6,%7}, {%8,%9}, {%0,%1,%2,%3};" \
                 : "+f"((d)[0]), "+f"((d)[1]), "+f"((d)[2]), "+f"((d)[3]) \
                 : "r"(a0), "r"(a1), "r"(a2), "r"(a3), "r"(b0), "r"(b1))

#define LDSM_X4(r, a) \
    asm volatile("ldmatrix.sync.aligned.m8n8.x4.shared.b16 {%0,%1,%2,%3}, [%4];" \
                 : "=r"((r)[0]), "=r"((r)[1]), "=r"((r)[2]), "=r"((r)[3]) : "r"(a))
#define LDSM_X2(r, a) \
    asm volatile("ldmatrix.sync.aligned.m8n8.x2.shared.b16 {%0,%1}, [%2];" \
                 : "=r"((r)[0]), "=r"((r)[1]) : "r"(a))

// ============== HMMA split-fp16 GEMM: C[M,N] = A2[M,K2] * B2[N,K2]^T ===========
// tile 128x128, BK=64, 2-stage cp.async, 8 warps (2x4) of 64x32.
// smem row stride 72 halves (144B): 8-row LDSM phases hit banks 4r (distinct).
#define BKC 64
#define SROW 72
#define STILE (128 * SROW)
#define NSTG 2
#define SMEM_DYN (NSTG * 2 * STILE * 2)    // 73728 bytes

struct HmmaCore {
    __device__ __forceinline__ static void run(
        const __half* gAbase, const __half* gBbase,
        float* C, int K2, int ldc, int bm, int bn, uint32_t sbase)
    {
        const int tid = threadIdx.x;
        const int lane = tid & 31, wid = tid >> 5;
        const int wm = wid >> 2;
        const int wn = wid & 3;
        const int grp = lane >> 2;
        const int qd  = lane & 3;
        const int NC = K2 / BKC;

        const int rA = lane & 15, hA = lane >> 4;
        const int rB = lane & 7,  hB = (lane >> 3) & 1;
        const uint32_t aAddr0 = sbase + (uint32_t)(((wm*64 + rA) * SROW + hA*8) * 2);
        const uint32_t bAddr0 = sbase + (uint32_t)(STILE*2) +
                                (uint32_t)(((wn*32 + rB) * SROW + hB*8) * 2);

        // loader: per operand 128 rows x 8 x 16B chunks = 1024 cp16; 4 per thread
        const int lrow = tid >> 1;
        const int lc4  = (tid & 1) * 4;          // chunk base (each chunk = 8 halves)
        const __half* gA = gAbase + (long long)(bm + lrow) * K2 + lc4 * 8;
        const __half* gB = gBbase + (long long)(bn + lrow) * K2 + lc4 * 8;
        const uint32_t sA0 = sbase + (uint32_t)((lrow * SROW + lc4 * 8) * 2);
        const uint32_t sB0 = sA0 + (uint32_t)(STILE * 2);

        auto load_chunk = [&](int c, int s) {
            uint32_t off = (uint32_t)(s * 2 * STILE * 2);
            const __half* pa = gA + (long long)c * BKC;
            const __half* pb = gB + (long long)c * BKC;
#pragma unroll
            for (int j = 0; j < 4; ++j) {
                cp16(sA0 + off + j * 16, pa + j * 8);
                cp16(sB0 + off + j * 16, pb + j * 8);
            }
            CP_COMMIT();
        };

        float acc[4][4][4];
#pragma unroll
        for (int i = 0; i < 4; i++)
#pragma unroll
            for (int j = 0; j < 4; j++)
#pragma unroll
                for (int r = 0; r < 4; r++) acc[i][j][r] = 0.f;

        load_chunk(0, 0);

        for (int c = 0; c < NC; ++c) {
            const int s = c & 1;
            if (c + 1 < NC) { load_chunk(c + 1, s ^ 1); CP_WAIT(1); }
            else            { CP_WAIT(0); }
            __syncthreads();

            const uint32_t soff = (uint32_t)(s * 2 * STILE * 2);
#pragma unroll
            for (int kk = 0; kk < 4; ++kk) {
                const uint32_t kbyte = kk * 32;
                uint32_t af[4][4];
#pragma unroll
                for (int mt = 0; mt < 4; ++mt)
                    LDSM_X4(af[mt], aAddr0 + soff + (uint32_t)(mt * 16 * SROW * 2) + kbyte);
                uint32_t bf[4][2];
#pragma unroll
                for (int nt = 0; nt < 4; ++nt)
                    LDSM_X2(bf[nt], bAddr0 + soff + (uint32_t)(nt * 8 * SROW * 2) + kbyte);
#pragma unroll
                for (int mt = 0; mt < 4; ++mt)
#pragma unroll
                    for (int nt = 0; nt < 4; ++nt)
                        MMA16816(acc[mt][nt], af[mt][0], af[mt][1], af[mt][2], af[mt][3],
                                 bf[nt][0], bf[nt][1]);
            }
            __syncthreads();
        }

#pragma unroll
        for (int mt = 0; mt < 4; ++mt) {
            int row0 = bm + wm * 64 + mt * 16 + grp;
#pragma unroll
            for (int nt = 0; nt < 4; ++nt) {
                int col = bn + wn * 32 + nt * 8 + qd * 2;
                *reinterpret_cast<float2*>(&C[(long long)row0 * ldc + col]) =
                    make_float2(acc[mt][nt][0], acc[mt][nt][1]);
                *reinterpret_cast<float2*>(&C[(long long)(row0 + 8) * ldc + col]) =
                    make_float2(acc[mt][nt][2], acc[mt][nt][3]);
            }
        }
    }
};

__global__ __launch_bounds__(256) void hmma_gemm(
    const __half* __restrict__ A, const __half* __restrict__ B,
    float* __restrict__ C, int K2, int ldc)
{
    extern __shared__ __half smdyn[];
    HmmaCore::run(A, B, C, K2, ldc, blockIdx.y * 128, blockIdx.x * 128,
                  (uint32_t)__cvta_generic_to_shared(smdyn));
}

// batched over z = e*NH + h: ke[e][tok][h*HD + :] = k2[h] @ Wek2[e,h]^T
__global__ __launch_bounds__(256) void hmma_gemm_ke(
    const __half* __restrict__ k2, const __half* __restrict__ Wek2,
    float* __restrict__ ke)
{
    extern __shared__ __half smdyn[];
    const int z = blockIdx.z;
    const int e = z >> 3, h = z & 7;
    const __half* A = k2  + (long long)h * TOK_ * (2*HD_);
    const __half* B = Wek2 + (long long)z * HD_ * (2*HD_);
    float* C = ke + (long long)e * TOK_ * KD_ + h * HD_;
    HmmaCore::run(A, B, C, 2*HD_, KD_, blockIdx.y * 128, blockIdx.x * 128,
                  (uint32_t)__cvta_generic_to_shared(smdyn));
}

// ---------------- fp32 -> split-fp16 pair layout (8 elems/thread) ---------------
struct alignas(16) H8 { __half v[8]; };

__global__ void split2_kernel(const float* __restrict__ src, __half* __restrict__ dst,
                              int K, int aSide)
{
    long long i8 = ((long long)blockIdx.x * 256 + threadIdx.x) * 8;
    int row = (int)(i8 / K);
    int col = (int)(i8 - (long long)row * K);
    float4 x0 = *reinterpret_cast<const float4*>(src + i8);
    float4 x1 = *reinterpret_cast<const float4*>(src + i8 + 4);
    float xs[8] = {x0.x, x0.y, x0.z, x0.w, x1.x, x1.y, x1.z, x1.w};
    H8 H, L;
#pragma unroll
    for (int j = 0; j < 8; ++j) {
        __half h = __float2half(xs[j]);
        H.v[j] = h;
        L.v[j] = __float2half(xs[j] - __half2float(h));
    }
    long long b = (long long)row * (2LL * K) + col;
    *reinterpret_cast<H8*>(dst + b)      = H;
    *reinterpret_cast<H8*>(dst + b + K)  = aSide ? L : H;
}

// -------- FUSED q/k path: conv(K=4)+SiLU -> l2norm -> q fp32 & k2 split-fp16 ----
__global__ __launch_bounds__(256) void fused_qk_kernel(
    const float* __restrict__ xqkvg, const float* __restrict__ cq,
    const float* __restrict__ ck, float* __restrict__ qout,
    __half* __restrict__ k2)
{
    const int tok = blockIdx.x;
    const int l = tok & (L_ - 1);
    const int tid = threadIdx.x;
    const int c0 = tid * 8;
    const int h = tid >> 5;
    const int d = c0 & 255;

    float ya[2][8];
#pragma unroll
    for (int op = 0; op < 2; ++op) {
        const float* wb = (op == 0) ? cq : ck;
        const int off = op * KD_;
        float acc[8];
#pragma unroll
        for (int j = 0; j < 8; ++j) acc[j] = 0.f;
#pragma unroll
        for (int tap = 0; tap < 4; ++tap) {
            int lt = l - 3 + tap;
            if (lt >= 0) {
                const float* xr = xqkvg + (long long)(tok - 3 + tap) * QKVG_ + off + c0;
                float4 a = *reinterpret_cast<const float4*>(xr);
                float4 b4 = *reinterpret_cast<const float4*>(xr + 4);
                float xs[8] = {a.x, a.y, a.z, a.w, b4.x, b4.y, b4.z, b4.w};
#pragma unroll
                for (int j = 0; j < 8; ++j)
                    acc[j] += wb[(c0 + j) * 4 + tap] * xs[j];
            }
        }
        float ss = 0.f;
#pragma unroll
        for (int j = 0; j < 8; ++j) {
            float y = acc[j] / (1.f + expf(-acc[j]));
            ya[op][j] = y;
            ss += y * y;
        }
#pragma unroll
        for (int o = 16; o; o >>= 1) ss += __shfl_xor_sync(0xffffffffu, ss, o);
        float r = rsqrtf(ss + 1e-6f);
        if (op == 0) r *= 0.0625f;
#pragma unroll
        for (int j = 0; j < 8; ++j) ya[op][j] *= r;
    }

    float4 q0 = make_float4(ya[0][0], ya[0][1], ya[0][2], ya[0][3]);
    float4 q1 = make_float4(ya[0][4], ya[0][5], ya[0][6], ya[0][7]);
    *reinterpret_cast<float4*>(qout + (long long)tok * KD_ + c0)     = q0;
    *reinterpret_cast<float4*>(qout + (long long)tok * KD_ + c0 + 4) = q1;

    H8 H, L;
#pragma unroll
    for (int j = 0; j < 8; ++j) {
        __half hb = __float2half(ya[1][j]);
        H.v[j] = hb;
        L.v[j] = __float2half(ya[1][j] - __half2float(hb));
    }
    long long b2 = ((long long)h * TOK_ + tok) * (2LL * HD_) + d;
    *reinterpret_cast<H8*>(k2 + b2)       = H;
    *reinterpret_cast<H8*>(k2 + b2 + HD_) = L;
}

// ------------- small projection: beta_raw / a_raw = X @ {Wb,Wa}^T ---------------
__global__ __launch_bounds__(256) void proj_ba_kernel(
    const float* __restrict__ X, const float* __restrict__ Wb, const float* __restrict__ Wa,
    float* __restrict__ outB, float* __restrict__ outA)
{
    __shared__ float xs[HS_];
    int tok = blockIdx.x;
    const float* xr = X + (long long)tok * HS_;
    for (int i = threadIdx.x * 4; i < HS_; i += 256 * 4)
        *reinterpret_cast<float4*>(&xs[i]) = *reinterpret_cast<const float4*>(&xr[i]);
    __syncthreads();
    int warp = threadIdx.x >> 5, lane = threadIdx.x & 31;
    for (int j = warp; j < E_ * NH_; j += 8) {
        const float* wb = Wb + (long long)j * HS_;
        const float* wa = Wa + (long long)j * HS_;
        float sb = 0.f, sa = 0.f;
        for (int i = lane * 4; i < HS_; i += 32 * 4) {
            float4 xv = *reinterpret_cast<const float4*>(&xs[i]);
            float4 bv = *reinterpret_cast<const float4*>(&wb[i]);
            float4 av = *reinterpret_cast<const float4*>(&wa[i]);
            sb += xv.x*bv.x + xv.y*bv.y + xv.z*bv.z + xv.w*bv.w;
            sa += xv.x*av.x + xv.y*av.y + xv.z*av.z + xv.w*av.w;
        }
#pragma unroll
        for (int off = 16; off; off >>= 1) {
            sb += __shfl_xor_sync(0xffffffffu, sb, off);
            sa += __shfl_xor_sync(0xffffffffu, sa, off);
        }
        if (lane == 0) {
            outB[tok * (E_*NH_) + j] = sb;
            outA[tok * (E_*NH_) + j] = sa;
        }
    }
}

// -------- causal depthwise conv (K=4) + SiLU; input row stride CS ---------------
__global__ void conv_silu_kernel(const float* __restrict__ xin, const float* __restrict__ w,
                                 float* __restrict__ out, int CS, int C)
{
    int c  = blockIdx.x * 256 + threadIdx.x;
    int b  = blockIdx.z;
    int l0 = blockIdx.y * 64;
    float w0 = w[c*4+0], w1 = w[c*4+1], w2 = w[c*4+2], w3 = w[c*4+3];
    const float* xb = xin + (long long)b * L_ * CS + c;
    float*       ob = out + (long long)b * L_ * C  + c;
    float xm3 = (l0 >= 3) ? xb[(long long)(l0-3)*CS] : 0.f;
    float xm2 = (l0 >= 2) ? xb[(long long)(l0-2)*CS] : 0.f;
    float xm1 = (l0 >= 1) ? xb[(long long)(l0-1)*CS] : 0.f;
    for (int l = l0; l < l0 + 64; ++l) {
        float x0 = xb[(long long)l*CS];
        float y  = w0*xm3 + w1*xm2 + w2*xm1 + w3*x0;
        ob[(long long)l*C] = y / (1.f + expf(-y));
        xm3 = xm2; xm2 = xm1; xm1 = x0;
    }
}

// ---------------- gating: decay and beta*mask per (e,b,h,t) --------------------
__global__ void gating_kernel(const float* __restrict__ betaA, const float* __restrict__ aA,
                              const int* __restrict__ mod, const float* __restrict__ A_log,
                              const float* __restrict__ dtb,
                              float* __restrict__ dec, float* __restrict__ bm)
{
    int idx = blockIdx.x * 256 + threadIdx.x;
    if (idx >= E_*B_*NH_*L_) return;
    int t = idx % L_;
    int h = (idx / L_) % NH_;
    int b = (idx / (L_*NH_)) % B_;
    int e = idx / (L_*NH_*B_);
    int tok = b * L_ + t;
    int j = e * NH_ + h;
    float braw = betaA[tok*(E_*NH_) + j];
    float beta = 1.f / (1.f + expf(-braw));
    float av = aA[tok*(E_*NH_) + j] + dtb[j];
    float sp = (av > 20.f) ? av : log1pf(expf(av));
    float g  = -expf(A_log[j]) * sp;
    int mid  = mod[tok];
    float m  = (e == 0) ? 1.f : ((e == 1) ? (mid == 0 ? 1.f : 0.f)
                                          : (mid == 1 ? 1.f : 0.f));
    dec[idx] = expf(g) * m + (1.f - m);
    bm[idx]  = beta * m;
}

// ---------------- zero fill -----------------------------------------------------
__global__ void zero_kernel(float4* __restrict__ p, int n4)
{
    int i = blockIdx.x * 256 + threadIdx.x;
    if (i < n4) p[i] = make_float4(0.f, 0.f, 0.f, 0.f);
}

// ---- recurrent scan: scalar register state, NO occupancy forcing (R7/R11 lesson)
__global__ __launch_bounds__(128) void scan_kernel(
    const float* __restrict__ qbuf, const float* __restrict__ kebuf,
    const float* __restrict__ vbuf, const float* __restrict__ decbuf,
    const float* __restrict__ bmbuf, const float* __restrict__ oww,
    float* __restrict__ opre)
{
    const int cta = blockIdx.x;
    const int vp = cta % NV_;
    const int h  = (cta / NV_) % NH_;
    const int b  = (cta / (NV_ * NH_)) % B_;
    const int e  = cta / (NV_ * NH_ * B_);
    const int tid = threadIdx.x;
    const int vl = tid >> 1;
    const int kh = tid & 1;

    float w0 = expf(oww[0*NH_ + h]);
    float w1 = expf(oww[1*NH_ + h]);
    float w2 = expf(oww[2*NH_ + h]);
    const float wout = ((e == 0) ? w0 : ((e == 1) ? w1 : w2)) / (w0 + w1 + w2);

    __shared__ __align__(16) float ksm[2][264];
    __shared__ __align__(16) float qsm[2][264];

    float S[128];
#pragma unroll
    for (int j = 0; j < 128; j++) S[j] = 0.f;

    const float* decp = decbuf + ((e*B_ + b)*NH_ + h) * L_;
    const float* bmp  = bmbuf  + ((e*B_ + b)*NH_ + h) * L_;
    const float* vp_  = vbuf  + (long long)b * L_ * VD_ + h * DV_ + vp * DVS_ + vl;
    float*       op   = opre  + (long long)b * L_ * VD_ + h * DV_ + vp * DVS_ + vl;

    const int koff = kh * 132;
    const int idx4 = tid & 63;
    const int halfoff = ((idx4 >> 5) * 132) + ((idx4 * 4) & 127);
    const bool loadk = (tid < 64);
    const float* msrc = (loadk
        ? (kebuf + (long long)e * TOK_ * KD_ + (long long)b * L_ * KD_ + h * HD_)
        : (qbuf + (long long)b * L_ * KD_ + h * HD_)) + idx4 * 4;

    {
        float4 v4 = *reinterpret_cast<const float4*>(msrc);
        float* dst = loadk ? &ksm[0][0] : &qsm[0][0];
        *reinterpret_cast<float4*>(dst + halfoff) = v4;
    }
    float dec_c = decp[0], bm_c = bmp[0], v_c = vp_[0];
    __syncthreads();

    for (int t = 0; t < L_; ++t) {
        const int cur = t & 1;
        float dec_n = 0.f, bm_n = 0.f, v_n = 0.f;
        if (t + 1 < L_) {
            msrc += KD_;
            float4 v4 = *reinterpret_cast<const float4*>(msrc);
            float* dst = loadk ? &ksm[cur ^ 1][0] : &qsm[cur ^ 1][0];
            *reinterpret_cast<float4*>(dst + halfoff) = v4;
            dec_n = decp[t+1]; bm_n = bmp[t+1]; v_n = vp_[(long long)(t+1) * VD_];
        }
        const float* kb = &ksm[cur][koff];
        const float* qb = &qsm[cur][koff];
        float o;

        if (bm_c != 0.f) {
            float p0 = 0.f, p1 = 0.f, p2 = 0.f, p3 = 0.f;
#pragma unroll
            for (int j = 0; j < 128; j += 4) {
                float4 kv = *reinterpret_cast<const float4*>(&kb[j]);
                S[j+0] *= dec_c; p0 += kv.x * S[j+0];
                S[j+1] *= dec_c; p1 += kv.y * S[j+1];
                S[j+2] *= dec_c; p2 += kv.z * S[j+2];
                S[j+3] *= dec_c; p3 += kv.w * S[j+3];
            }
            float pred = (p0 + p1) + (p2 + p3);
            pred += __shfl_xor_sync(0xffffffffu, pred, 1);
            float delta = (v_c - pred) * bm_c;

            float o0 = 0.f, o1 = 0.f, o2 = 0.f, o3 = 0.f;
#pragma unroll
            for (int j = 0; j < 128; j += 4) {
                float4 kv = *reinterpret_cast<const float4*>(&kb[j]);
                float4 qv = *reinterpret_cast<const float4*>(&qb[j]);
                S[j+0] += kv.x * delta; o0 += qv.x * S[j+0];
                S[j+1] += kv.y * delta; o1 += qv.y * S[j+1];
                S[j+2] += kv.z * delta; o2 += qv.z * S[j+2];
                S[j+3] += kv.w * delta; o3 += qv.w * S[j+3];
            }
            o = (o0 + o1) + (o2 + o3);
        } else {
            float o0 = 0.f, o1 = 0.f, o2 = 0.f, o3 = 0.f;
#pragma unroll
            for (int j = 0; j < 128; j += 4) {
                float4 qv = *reinterpret_cast<const float4*>(&qb[j]);
                o0 += qv.x * S[j+0];
                o1 += qv.y * S[j+1];
                o2 += qv.z * S[j+2];
                o3 += qv.w * S[j+3];
            }
            o = (o0 + o1) + (o2 + o3);
        }
        o += __shfl_xor_sync(0xffffffffu, o, 1);
        if (kh == 0) atomicAdd(&op[(long long)t * VD_], o * wout);

        __syncthreads();
        dec_c = dec_n; bm_c = bm_n; v_c = v_n;
    }
}

// -------- RMSNorm * weight * SiLU(gate), emitting split-fp16 A-operand ----------
__global__ __launch_bounds__(128) void norm_gate_kernel(
    const float* __restrict__ opre, const float* __restrict__ xqkvg,
    const float* __restrict__ wnorm, __half* __restrict__ out2)
{
    int row = blockIdx.x;                       // tok*NH + h
    int tok = row >> 3;
    int hh  = row & 7;
    long long base = (long long)row * DV_;
    const float* o = opre + base;
    const float* g = xqkvg + (long long)tok * QKVG_ + (2*KD_ + VD_) + hh * DV_;
    int i = threadIdx.x * 4;
    float4 ov = *reinterpret_cast<const float4*>(&o[i]);
    float ss = ov.x*ov.x + ov.y*ov.y + ov.z*ov.z + ov.w*ov.w;
#pragma unroll
    for (int off = 16; off; off >>= 1) ss += __shfl_xor_sync(0xffffffffu, ss, off);
    __shared__ float red[4];
    int warp = threadIdx.x >> 5, lane = threadIdx.x & 31;
    if (lane == 0) red[warp] = ss;
    __syncthreads();
    float tot = red[0] + red[1] + red[2] + red[3];
    float inv = rsqrtf(tot * (1.f / (float)DV_) + 1e-5f);
    float4 wv = *reinterpret_cast<const float4*>(&wnorm[i]);
    float4 gv = *reinterpret_cast<const float4*>(&g[i]);
    float r[4];
    r[0] = ov.x * inv * wv.x * (gv.x / (1.f + expf(-gv.x)));
    r[1] = ov.y * inv * wv.y * (gv.y / (1.f + expf(-gv.y)));
    r[2] = ov.z * inv * wv.z * (gv.z / (1.f + expf(-gv.z)));
    r[3] = ov.w * inv * wv.w * (gv.w / (1.f + expf(-gv.w)));
    int col = hh * DV_ + i;
    long long b2 = (long long)tok * (2LL * VD_) + col;
#pragma unroll
    for (int j = 0; j < 4; ++j) {
        __half hb = __float2half(r[j]);
        __half lb = __float2half(r[j] - __half2float(hb));
        out2[b2 + j]       = hb;
        out2[b2 + VD_ + j] = lb;
    }
}

// ================================ launch ======================================
extern "C" void kernel_launch(void* const* d_in, const int* in_sizes, int n_in,
                              void* d_out, int out_size)
{
    const float* X    = (const float*)d_in[0];
    const int*   mod  = (const int*)  d_in[1];
    const float* Wq   = (const float*)d_in[2];
    const float* Wk   = (const float*)d_in[3];
    const float* Wv   = (const float*)d_in[4];
    const float* cq   = (const float*)d_in[5];
    const float* ck   = (const float*)d_in[6];
    const float* cv   = (const float*)d_in[7];
    const float* Wek  = (const float*)d_in[8];
    const float* Wb   = (const float*)d_in[9];
    const float* Wa   = (const float*)d_in[10];
    const float* Alog = (const float*)d_in[11];
    const float* dtb  = (const float*)d_in[12];
    const float* ow   = (const float*)d_in[13];
    const float* Wg   = (const float*)d_in[14];
    const float* onw  = (const float*)d_in[15];
    const float* Wo   = (const float*)d_in[16];
    float* out = (float*)d_out;

    float *xqkvg, *q, *v, *ke, *ba, *aa, *dec, *bm, *opre;
    __half *X2, *Wqkvg2, *Wo2, *of2, *k2, *Wek2;
    cudaGetSymbolAddress((void**)&xqkvg, g_xqkvg);
    cudaGetSymbolAddress((void**)&q,     g_q);
    cudaGetSymbolAddress((void**)&v,     g_v);
    cudaGetSymbolAddress((void**)&ke,    g_ke);
    cudaGetSymbolAddress((void**)&ba,    g_betaA);
    cudaGetSymbolAddress((void**)&aa,    g_aA);
    cudaGetSymbolAddress((void**)&dec,   g_dec);
    cudaGetSymbolAddress((void**)&bm,    g_bm);
    cudaGetSymbolAddress((void**)&opre,  g_opre);
    cudaGetSymbolAddress((void**)&X2,    g_X2);
    cudaGetSymbolAddress((void**)&Wqkvg2,g_Wqkvg2);
    cudaGetSymbolAddress((void**)&Wo2,   g_Wo2);
    cudaGetSymbolAddress((void**)&of2,   g_of2);
    cudaGetSymbolAddress((void**)&k2,    g_k2);
    cudaGetSymbolAddress((void**)&Wek2,  g_Wek2);

    cudaFuncSetAttribute(hmma_gemm,    cudaFuncAttributeMaxDynamicSharedMemorySize, SMEM_DYN);
    cudaFuncSetAttribute(hmma_gemm_ke, cudaFuncAttributeMaxDynamicSharedMemorySize, SMEM_DYN);

    // launches 0-4: splits needed by the projection GEMM
    split2_kernel<<<TOK_*HS_/2048, 256>>>(X,  X2, HS_, 1);
    split2_kernel<<<KD_*HS_/2048, 256>>>(Wq, Wqkvg2,                                 HS_, 0);
    split2_kernel<<<KD_*HS_/2048, 256>>>(Wk, Wqkvg2 + (long long)KD_*2*HS_,          HS_, 0);
    split2_kernel<<<VD_*HS_/2048, 256>>>(Wv, Wqkvg2 + (long long)(2*KD_)*2*HS_,      HS_, 0);
    split2_kernel<<<VD_*HS_/2048, 256>>>(Wg, Wqkvg2 + (long long)(2*KD_+VD_)*2*HS_,  HS_, 0);

    // launch 5 (ncu -s 5 -c 1 profiles THIS): merged projection GEMM
    hmma_gemm<<<dim3(QKVG_/128, TOK_/128), 256, SMEM_DYN>>>(X2, Wqkvg2, xqkvg, 2*HS_, QKVG_);

    // remaining splits (consumers come later)
    split2_kernel<<<HS_*VD_/2048, 256>>>(Wo, Wo2, VD_, 0);
    split2_kernel<<<E_*NH_*HD_*HD_/2048, 256>>>(Wek, Wek2, HD_, 0);

    proj_ba_kernel<<<TOK_, 256>>>(X, Wb, Wa, ba, aa);

    // fused conv+silu+l2norm for q,k (writes q fp32 + k2 split-fp16 directly)
    fused_qk_kernel<<<TOK_, 256>>>(xqkvg, cq, ck, q, k2);

    // conv + SiLU for v
    conv_silu_kernel<<<dim3(VD_/256, L_/64, B_), 256>>>(xqkvg + 2*KD_,  cv, v, QKVG_, VD_);

    // per-expert per-head key transform on HMMA (batched over e,h; K2 = 512)
    hmma_gemm_ke<<<dim3(HD_/128, TOK_/128, E_*NH_), 256, SMEM_DYN>>>(k2, Wek2, ke);

    // gating scalars
    gating_kernel<<<(E_*B_*NH_*L_ + 255)/256, 256>>>(ba, aa, mod, Alog, dtb, dec, bm);

    // zero the expert-aggregated output accumulator
    zero_kernel<<<(TOK_*VD_/4 + 255)/256, 256>>>((float4*)opre, TOK_*VD_/4);

    // the sequential scan (scalar state, natural occupancy)
    scan_kernel<<<E_*B_*NH_*NV_, 128>>>(q, ke, v, dec, bm, ow, opre);

    // RMSNorm + swish gate -> split-fp16 A operand
    norm_gate_kernel<<<TOK_*NH_, 128>>>(opre, xqkvg, onw, of2);

    // output projection (K2 = 2*VD = 8192)
    hmma_gemm<<<dim3(HS_/128, TOK_/128), 256, SMEM_DYN>>>(of2, Wo2, out, 2*VD_, HS_);
}

// round 15
// speedup vs baseline: 1.0413x; 1.0413x over previous
#include <cuda_runtime.h>
#include <cuda_fp16.h>
#include <cstdint>
#include <math.h>

#define B_   2
#define L_   1024
#define HS_  2048
#define NH_  8
#define HD_  256
#define DV_  512
#define KD_  2048
#define VD_  4096
#define E_   3
#define TOK_ 2048
#define NV_  8
#define DVS_ 64
#define QKVG_ 12288    // merged row: q(2048) k(2048) v(4096) g(4096)

// ---------------- scratch (static device arrays; no allocation) ----------------
__device__ __align__(16) float g_xqkvg[TOK_*QKVG_];
__device__ __align__(16) float g_q [TOK_*KD_];
__device__ __align__(16) float g_v [TOK_*VD_];
__device__ __align__(16) float g_ke[E_*TOK_*KD_];
__device__ __align__(16) float g_betaA[TOK_*E_*NH_];
__device__ __align__(16) float g_aA  [TOK_*E_*NH_];
__device__ __align__(16) float g_dec [E_*B_*NH_*L_];
__device__ __align__(16) float g_bm  [E_*B_*NH_*L_];
__device__ __align__(16) float g_opre3[E_*TOK_*VD_];   // per-expert output slabs

// split-fp16 buffers: A-side layout [hi | lo], B-side layout [hi | hi]
__device__ __align__(16) __half g_X2    [TOK_*2*HS_];
__device__ __align__(16) __half g_Wqkvg2[QKVG_*2*HS_];
__device__ __align__(16) __half g_Wo2   [HS_*2*VD_];
__device__ __align__(16) __half g_of2   [TOK_*2*VD_];
__device__ __align__(16) __half g_k2    [NH_*TOK_*2*HD_];
__device__ __align__(16) __half g_Wek2  [E_*NH_*HD_*2*HD_];

// ======================= helpers =============================================
__device__ __forceinline__ void cp16(uint32_t dst, const void* src) {
    asm volatile("cp.async.cg.shared.global [%0], [%1], 16;" :: "r"(dst), "l"(src));
}
#define CP_COMMIT() asm volatile("cp.async.commit_group;" ::: "memory")
#define CP_WAIT(n)  asm volatile("cp.async.wait_group %0;" :: "n"(n) : "memory")

#define MMA16816(d, a0, a1, a2, a3, b0, b1) \
    asm volatile("mma.sync.aligned.m16n8k16.row.col.f32.f16.f16.f32 " \
                 "{%0,%1,%2,%3}, {%4,%5,%6,%7}, {%8,%9}, {%0,%1,%2,%3};" \
                 : "+f"((d)[0]), "+f"((d)[1]), "+f"((d)[2]), "+f"((d)[3]) \
                 : "r"(a0), "r"(a1), "r"(a2), "r"(a3), "r"(b0), "r"(b1))

#define LDSM_X4(r, a) \
    asm volatile("ldmatrix.sync.aligned.m8n8.x4.shared.b16 {%0,%1,%2,%3}, [%4];" \
                 : "=r"((r)[0]), "=r"((r)[1]), "=r"((r)[2]), "=r"((r)[3]) : "r"(a))
#define LDSM_X2(r, a) \
    asm volatile("ldmatrix.sync.aligned.m8n8.x2.shared.b16 {%0,%1}, [%2];" \
                 : "=r"((r)[0]), "=r"((r)[1]) : "r"(a))

// ============== HMMA split-fp16 GEMM (R13 config: BK=32, 3-stage) ==============
#define BKC 32
#define SROW 40
#define STILE (128 * SROW)
#define NSTG 3
#define SMEM_DYN (NSTG * 2 * STILE * 2)    // 61440 bytes

struct HmmaCore {
    __device__ __forceinline__ static void run(
        const __half* gAbase, const __half* gBbase,
        float* C, int K2, int ldc, int bm, int bn, uint32_t sbase)
    {
        const int tid = threadIdx.x;
        const int lane = tid & 31, wid = tid >> 5;
        const int wm = wid >> 2;
        const int wn = wid & 3;
        const int grp = lane >> 2;
        const int qd  = lane & 3;
        const int NC = K2 / BKC;

        const int rA = lane & 15, hA = lane >> 4;
        const int rB = lane & 7,  hB = (lane >> 3) & 1;
        const uint32_t aAddr0 = sbase + (uint32_t)(((wm*64 + rA) * SROW + hA*8) * 2);
        const uint32_t bAddr0 = sbase + (uint32_t)(STILE*2) +
                                (uint32_t)(((wn*32 + rB) * SROW + hB*8) * 2);

        const int lrow = tid >> 1;
        const int lch2 = (tid & 1) * 2;
        const __half* gA = gAbase + (long long)(bm + lrow) * K2 + lch2 * 8;
        const __half* gB = gBbase + (long long)(bn + lrow) * K2 + lch2 * 8;
        const uint32_t sA0 = sbase + (uint32_t)((lrow * SROW + lch2 * 8) * 2);
        const uint32_t sB0 = sA0 + (uint32_t)(STILE * 2);

        auto load_chunk = [&](int c, int s) {
            uint32_t off = (uint32_t)(s * 2 * STILE * 2);
            const __half* pa = gA + (long long)c * BKC;
            const __half* pb = gB + (long long)c * BKC;
            cp16(sA0 + off,      pa);
            cp16(sA0 + off + 16, pa + 8);
            cp16(sB0 + off,      pb);
            cp16(sB0 + off + 16, pb + 8);
            CP_COMMIT();
        };

        float acc[4][4][4];
#pragma unroll
        for (int i = 0; i < 4; i++)
#pragma unroll
            for (int j = 0; j < 4; j++)
#pragma unroll
                for (int r = 0; r < 4; r++) acc[i][j][r] = 0.f;

        load_chunk(0, 0);
        if (NC > 1) load_chunk(1, 1);

        for (int c = 0; c < NC; ++c) {
            const int s = c % NSTG;
            if (c + 2 < NC) { load_chunk(c + 2, (c + 2) % NSTG); CP_WAIT(2); }
            else if (c + 1 < NC) { CP_WAIT(1); }
            else { CP_WAIT(0); }
            __syncthreads();

            const uint32_t soff = (uint32_t)(s * 2 * STILE * 2);
#pragma unroll
            for (int kk = 0; kk < 2; ++kk) {
                const uint32_t kbyte = kk * 32;
                uint32_t af[4][4];
#pragma unroll
                for (int mt = 0; mt < 4; ++mt)
                    LDSM_X4(af[mt], aAddr0 + soff + (uint32_t)(mt * 16 * SROW * 2) + kbyte);
                uint32_t bf[4][2];
#pragma unroll
                for (int nt = 0; nt < 4; ++nt)
                    LDSM_X2(bf[nt], bAddr0 + soff + (uint32_t)(nt * 8 * SROW * 2) + kbyte);
#pragma unroll
                for (int mt = 0; mt < 4; ++mt)
#pragma unroll
                    for (int nt = 0; nt < 4; ++nt)
                        MMA16816(acc[mt][nt], af[mt][0], af[mt][1], af[mt][2], af[mt][3],
                                 bf[nt][0], bf[nt][1]);
            }
            __syncthreads();
        }

#pragma unroll
        for (int mt = 0; mt < 4; ++mt) {
            int row0 = bm + wm * 64 + mt * 16 + grp;
#pragma unroll
            for (int nt = 0; nt < 4; ++nt) {
                int col = bn + wn * 32 + nt * 8 + qd * 2;
                *reinterpret_cast<float2*>(&C[(long long)row0 * ldc + col]) =
                    make_float2(acc[mt][nt][0], acc[mt][nt][1]);
                *reinterpret_cast<float2*>(&C[(long long)(row0 + 8) * ldc + col]) =
                    make_float2(acc[mt][nt][2], acc[mt][nt][3]);
            }
        }
    }
};

__global__ __launch_bounds__(256) void hmma_gemm(
    const __half* __restrict__ A, const __half* __restrict__ B,
    float* __restrict__ C, int K2, int ldc)
{
    extern __shared__ __half smdyn[];
    HmmaCore::run(A, B, C, K2, ldc, blockIdx.y * 128, blockIdx.x * 128,
                  (uint32_t)__cvta_generic_to_shared(smdyn));
}

// batched over z = e*NH + h: ke[e][tok][h*HD + :] = k2[h] @ Wek2[e,h]^T
__global__ __launch_bounds__(256) void hmma_gemm_ke(
    const __half* __restrict__ k2, const __half* __restrict__ Wek2,
    float* __restrict__ ke)
{
    extern __shared__ __half smdyn[];
    const int z = blockIdx.z;
    const int e = z >> 3, h = z & 7;
    const __half* A = k2  + (long long)h * TOK_ * (2*HD_);
    const __half* B = Wek2 + (long long)z * HD_ * (2*HD_);
    float* C = ke + (long long)e * TOK_ * KD_ + h * HD_;
    HmmaCore::run(A, B, C, 2*HD_, KD_, blockIdx.y * 128, blockIdx.x * 128,
                  (uint32_t)__cvta_generic_to_shared(smdyn));
}

// ---------------- fp32 -> split-fp16 pair layout (8 elems/thread) ---------------
struct alignas(16) H8 { __half v[8]; };

__global__ void split2_kernel(const float* __restrict__ src, __half* __restrict__ dst,
                              int K, int aSide)
{
    long long i8 = ((long long)blockIdx.x * 256 + threadIdx.x) * 8;
    int row = (int)(i8 / K);
    int col = (int)(i8 - (long long)row * K);
    float4 x0 = *reinterpret_cast<const float4*>(src + i8);
    float4 x1 = *reinterpret_cast<const float4*>(src + i8 + 4);
    float xs[8] = {x0.x, x0.y, x0.z, x0.w, x1.x, x1.y, x1.z, x1.w};
    H8 H, L;
#pragma unroll
    for (int j = 0; j < 8; ++j) {
        __half h = __float2half(xs[j]);
        H.v[j] = h;
        L.v[j] = __float2half(xs[j] - __half2float(h));
    }
    long long b = (long long)row * (2LL * K) + col;
    *reinterpret_cast<H8*>(dst + b)      = H;
    *reinterpret_cast<H8*>(dst + b + K)  = aSide ? L : H;
}

// -------- FUSED q/k path: conv(K=4)+SiLU -> l2norm -> q fp32 & k2 split-fp16 ----
__global__ __launch_bounds__(256) void fused_qk_kernel(
    const float* __restrict__ xqkvg, const float* __restrict__ cq,
    const float* __restrict__ ck, float* __restrict__ qout,
    __half* __restrict__ k2)
{
    const int tok = blockIdx.x;
    const int l = tok & (L_ - 1);
    const int tid = threadIdx.x;
    const int c0 = tid * 8;
    const int h = tid >> 5;
    const int d = c0 & 255;

    float ya[2][8];
#pragma unroll
    for (int op = 0; op < 2; ++op) {
        const float* wb = (op == 0) ? cq : ck;
        const int off = op * KD_;
        float acc[8];
#pragma unroll
        for (int j = 0; j < 8; ++j) acc[j] = 0.f;
#pragma unroll
        for (int tap = 0; tap < 4; ++tap) {
            int lt = l - 3 + tap;
            if (lt >= 0) {
                const float* xr = xqkvg + (long long)(tok - 3 + tap) * QKVG_ + off + c0;
                float4 a = *reinterpret_cast<const float4*>(xr);
                float4 b4 = *reinterpret_cast<const float4*>(xr + 4);
                float xs[8] = {a.x, a.y, a.z, a.w, b4.x, b4.y, b4.z, b4.w};
#pragma unroll
                for (int j = 0; j < 8; ++j)
                    acc[j] += wb[(c0 + j) * 4 + tap] * xs[j];
            }
        }
        float ss = 0.f;
#pragma unroll
        for (int j = 0; j < 8; ++j) {
            float y = acc[j] / (1.f + expf(-acc[j]));
            ya[op][j] = y;
            ss += y * y;
        }
#pragma unroll
        for (int o = 16; o; o >>= 1) ss += __shfl_xor_sync(0xffffffffu, ss, o);
        float r = rsqrtf(ss + 1e-6f);
        if (op == 0) r *= 0.0625f;
#pragma unroll
        for (int j = 0; j < 8; ++j) ya[op][j] *= r;
    }

    float4 q0 = make_float4(ya[0][0], ya[0][1], ya[0][2], ya[0][3]);
    float4 q1 = make_float4(ya[0][4], ya[0][5], ya[0][6], ya[0][7]);
    *reinterpret_cast<float4*>(qout + (long long)tok * KD_ + c0)     = q0;
    *reinterpret_cast<float4*>(qout + (long long)tok * KD_ + c0 + 4) = q1;

    H8 H, L;
#pragma unroll
    for (int j = 0; j < 8; ++j) {
        __half hb = __float2half(ya[1][j]);
        H.v[j] = hb;
        L.v[j] = __float2half(ya[1][j] - __half2float(hb));
    }
    long long b2 = ((long long)h * TOK_ + tok) * (2LL * HD_) + d;
    *reinterpret_cast<H8*>(k2 + b2)       = H;
    *reinterpret_cast<H8*>(k2 + b2 + HD_) = L;
}

// ------ beta/a projection, W-traffic-efficient: CTA = 8 tokens, streams W once --
// 256 threads (8 warps). X rows for 8 tokens cached in smem (64KB).
// warp w computes j = {w, w+8, w+16} for all 8 tokens.
__global__ __launch_bounds__(256) void proj_ba_kernel(
    const float* __restrict__ X, const float* __restrict__ Wb, const float* __restrict__ Wa,
    float* __restrict__ outB, float* __restrict__ outA)
{
    extern __shared__ float xs8[];              // [8][HS_]
    const int tok0 = blockIdx.x * 8;
    const int tid = threadIdx.x;
    const int warp = tid >> 5, lane = tid & 31;

    // load 8 token rows (8*2048 floats = 4096 float4, 16 per thread)
    for (int i = tid * 4; i < 8 * HS_; i += 256 * 4)
        *reinterpret_cast<float4*>(&xs8[i]) =
            *reinterpret_cast<const float4*>(X + (long long)tok0 * HS_ + i);
    __syncthreads();

#pragma unroll
    for (int jj = 0; jj < 3; ++jj) {
        const int j = jj * 8 + warp;            // 0..23
        const float* wbr = Wb + (long long)j * HS_;
        const float* war = Wa + (long long)j * HS_;
        float sb[8], sa[8];
#pragma unroll
        for (int t = 0; t < 8; ++t) { sb[t] = 0.f; sa[t] = 0.f; }
        for (int i = lane * 4; i < HS_; i += 32 * 4) {
            float4 bv = *reinterpret_cast<const float4*>(&wbr[i]);
            float4 av = *reinterpret_cast<const float4*>(&war[i]);
#pragma unroll
            for (int t = 0; t < 8; ++t) {
                float4 xv = *reinterpret_cast<const float4*>(&xs8[t * HS_ + i]);
                sb[t] += xv.x*bv.x + xv.y*bv.y + xv.z*bv.z + xv.w*bv.w;
                sa[t] += xv.x*av.x + xv.y*av.y + xv.z*av.z + xv.w*av.w;
            }
        }
#pragma unroll
        for (int t = 0; t < 8; ++t) {
#pragma unroll
            for (int off = 16; off; off >>= 1) {
                sb[t] += __shfl_xor_sync(0xffffffffu, sb[t], off);
                sa[t] += __shfl_xor_sync(0xffffffffu, sa[t], off);
            }
            if (lane == 0) {
                outB[(tok0 + t) * (E_*NH_) + j] = sb[t];
                outA[(tok0 + t) * (E_*NH_) + j] = sa[t];
            }
        }
    }
}

// -------- causal depthwise conv (K=4) + SiLU; input row stride CS ---------------
__global__ void conv_silu_kernel(const float* __restrict__ xin, const float* __restrict__ w,
                                 float* __restrict__ out, int CS, int C)
{
    int c  = blockIdx.x * 256 + threadIdx.x;
    int b  = blockIdx.z;
    int l0 = blockIdx.y * 64;
    float w0 = w[c*4+0], w1 = w[c*4+1], w2 = w[c*4+2], w3 = w[c*4+3];
    const float* xb = xin + (long long)b * L_ * CS + c;
    float*       ob = out + (long long)b * L_ * C  + c;
    float xm3 = (l0 >= 3) ? xb[(long long)(l0-3)*CS] : 0.f;
    float xm2 = (l0 >= 2) ? xb[(long long)(l0-2)*CS] : 0.f;
    float xm1 = (l0 >= 1) ? xb[(long long)(l0-1)*CS] : 0.f;
    for (int l = l0; l < l0 + 64; ++l) {
        float x0 = xb[(long long)l*CS];
        float y  = w0*xm3 + w1*xm2 + w2*xm1 + w3*x0;
        ob[(long long)l*C] = y / (1.f + expf(-y));
        xm3 = xm2; xm2 = xm1; xm1 = x0;
    }
}

// ---------------- gating: decay and beta*mask per (e,b,h,t) --------------------
__global__ void gating_kernel(const float* __restrict__ betaA, const float* __restrict__ aA,
                              const int* __restrict__ mod, const float* __restrict__ A_log,
                              const float* __restrict__ dtb,
                              float* __restrict__ dec, float* __restrict__ bm)
{
    int idx = blockIdx.x * 256 + threadIdx.x;
    if (idx >= E_*B_*NH_*L_) return;
    int t = idx % L_;
    int h = (idx / L_) % NH_;
    int b = (idx / (L_*NH_)) % B_;
    int e = idx / (L_*NH_*B_);
    int tok = b * L_ + t;
    int j = e * NH_ + h;
    float braw = betaA[tok*(E_*NH_) + j];
    float beta = 1.f / (1.f + expf(-braw));
    float av = aA[tok*(E_*NH_) + j] + dtb[j];
    float sp = (av > 20.f) ? av : log1pf(expf(av));
    float g  = -expf(A_log[j]) * sp;
    int mid  = mod[tok];
    float m  = (e == 0) ? 1.f : ((e == 1) ? (mid == 0 ? 1.f : 0.f)
                                          : (mid == 1 ? 1.f : 0.f));
    dec[idx] = expf(g) * m + (1.f - m);
    bm[idx]  = beta * m;
}

// ---- recurrent scan: scalar state, direct per-expert stores (no atomics) -------
__global__ __launch_bounds__(128) void scan_kernel(
    const float* __restrict__ qbuf, const float* __restrict__ kebuf,
    const float* __restrict__ vbuf, const float* __restrict__ decbuf,
    const float* __restrict__ bmbuf, const float* __restrict__ oww,
    float* __restrict__ opre3)
{
    const int cta = blockIdx.x;
    const int vp = cta % NV_;
    const int h  = (cta / NV_) % NH_;
    const int b  = (cta / (NV_ * NH_)) % B_;
    const int e  = cta / (NV_ * NH_ * B_);
    const int tid = threadIdx.x;
    const int vl = tid >> 1;
    const int kh = tid & 1;

    float w0 = expf(oww[0*NH_ + h]);
    float w1 = expf(oww[1*NH_ + h]);
    float w2 = expf(oww[2*NH_ + h]);
    const float wout = ((e == 0) ? w0 : ((e == 1) ? w1 : w2)) / (w0 + w1 + w2);

    __shared__ __align__(16) float ksm[2][264];
    __shared__ __align__(16) float qsm[2][264];

    float S[128];
#pragma unroll
    for (int j = 0; j < 128; j++) S[j] = 0.f;

    const float* decp = decbuf + ((e*B_ + b)*NH_ + h) * L_;
    const float* bmp  = bmbuf  + ((e*B_ + b)*NH_ + h) * L_;
    const float* vp_  = vbuf  + (long long)b * L_ * VD_ + h * DV_ + vp * DVS_ + vl;
    float*       op   = opre3 + (long long)e * TOK_ * VD_
                              + (long long)b * L_ * VD_ + h * DV_ + vp * DVS_ + vl;

    const int koff = kh * 132;
    const int idx4 = tid & 63;
    const int halfoff = ((idx4 >> 5) * 132) + ((idx4 * 4) & 127);
    const bool loadk = (tid < 64);
    const float* msrc = (loadk
        ? (kebuf + (long long)e * TOK_ * KD_ + (long long)b * L_ * KD_ + h * HD_)
        : (qbuf + (long long)b * L_ * KD_ + h * HD_)) + idx4 * 4;

    {
        float4 v4 = *reinterpret_cast<const float4*>(msrc);
        float* dst = loadk ? &ksm[0][0] : &qsm[0][0];
        *reinterpret_cast<float4*>(dst + halfoff) = v4;
    }
    float dec_c = decp[0], bm_c = bmp[0], v_c = vp_[0];
    __syncthreads();

    for (int t = 0; t < L_; ++t) {
        const int cur = t & 1;
        float dec_n = 0.f, bm_n = 0.f, v_n = 0.f;
        if (t + 1 < L_) {
            msrc += KD_;
            float4 v4 = *reinterpret_cast<const float4*>(msrc);
            float* dst = loadk ? &ksm[cur ^ 1][0] : &qsm[cur ^ 1][0];
            *reinterpret_cast<float4*>(dst + halfoff) = v4;
            dec_n = decp[t+1]; bm_n = bmp[t+1]; v_n = vp_[(long long)(t+1) * VD_];
        }
        const float* kb = &ksm[cur][koff];
        const float* qb = &qsm[cur][koff];
        float o;

        if (bm_c != 0.f) {
            float p0 = 0.f, p1 = 0.f, p2 = 0.f, p3 = 0.f;
#pragma unroll
            for (int j = 0; j < 128; j += 4) {
                float4 kv = *reinterpret_cast<const float4*>(&kb[j]);
                S[j+0] *= dec_c; p0 += kv.x * S[j+0];
                S[j+1] *= dec_c; p1 += kv.y * S[j+1];
                S[j+2] *= dec_c; p2 += kv.z * S[j+2];
                S[j+3] *= dec_c; p3 += kv.w * S[j+3];
            }
            float pred = (p0 + p1) + (p2 + p3);
            pred += __shfl_xor_sync(0xffffffffu, pred, 1);
            float delta = (v_c - pred) * bm_c;

            float o0 = 0.f, o1 = 0.f, o2 = 0.f, o3 = 0.f;
#pragma unroll
            for (int j = 0; j < 128; j += 4) {
                float4 kv = *reinterpret_cast<const float4*>(&kb[j]);
                float4 qv = *reinterpret_cast<const float4*>(&qb[j]);
                S[j+0] += kv.x * delta; o0 += qv.x * S[j+0];
                S[j+1] += kv.y * delta; o1 += qv.y * S[j+1];
                S[j+2] += kv.z * delta; o2 += qv.z * S[j+2];
                S[j+3] += kv.w * delta; o3 += qv.w * S[j+3];
            }
            o = (o0 + o1) + (o2 + o3);
        } else {
            float o0 = 0.f, o1 = 0.f, o2 = 0.f, o3 = 0.f;
#pragma unroll
            for (int j = 0; j < 128; j += 4) {
                float4 qv = *reinterpret_cast<const float4*>(&qb[j]);
                o0 += qv.x * S[j+0];
                o1 += qv.y * S[j+1];
                o2 += qv.z * S[j+2];
                o3 += qv.w * S[j+3];
            }
            o = (o0 + o1) + (o2 + o3);
        }
        o += __shfl_xor_sync(0xffffffffu, o, 1);
        if (kh == 0) op[(long long)t * VD_] = o * wout;   // direct store, no atomic

        __syncthreads();
        dec_c = dec_n; bm_c = bm_n; v_c = v_n;
    }
}

// --- RMSNorm * weight * SiLU(gate) over summed expert slabs -> split-fp16 -------
__global__ __launch_bounds__(128) void norm_gate_kernel(
    const float* __restrict__ opre3, const float* __restrict__ xqkvg,
    const float* __restrict__ wnorm, __half* __restrict__ out2)
{
    int row = blockIdx.x;                       // tok*NH + h
    int tok = row >> 3;
    int hh  = row & 7;
    long long base = (long long)row * DV_;      // == tok*VD + h*DV
    const float* g = xqkvg + (long long)tok * QKVG_ + (2*KD_ + VD_) + hh * DV_;
    int i = threadIdx.x * 4;
    float4 o0 = *reinterpret_cast<const float4*>(opre3 + base + i);
    float4 o1 = *reinterpret_cast<const float4*>(opre3 + (long long)TOK_*VD_ + base + i);
    float4 o2 = *reinterpret_cast<const float4*>(opre3 + 2LL*TOK_*VD_ + base + i);
    float4 ov = make_float4(o0.x + o1.x + o2.x, o0.y + o1.y + o2.y,
                            o0.z + o1.z + o2.z, o0.w + o1.w + o2.w);
    float ss = ov.x*ov.x + ov.y*ov.y + ov.z*ov.z + ov.w*ov.w;
#pragma unroll
    for (int off = 16; off; off >>= 1) ss += __shfl_xor_sync(0xffffffffu, ss, off);
    __shared__ float red[4];
    int warp = threadIdx.x >> 5, lane = threadIdx.x & 31;
    if (lane == 0) red[warp] = ss;
    __syncthreads();
    float tot = red[0] + red[1] + red[2] + red[3];
    float inv = rsqrtf(tot * (1.f / (float)DV_) + 1e-5f);
    float4 wv = *reinterpret_cast<const float4*>(&wnorm[i]);
    float4 gv = *reinterpret_cast<const float4*>(&g[i]);
    float r[4];
    r[0] = ov.x * inv * wv.x * (gv.x / (1.f + expf(-gv.x)));
    r[1] = ov.y * inv * wv.y * (gv.y / (1.f + expf(-gv.y)));
    r[2] = ov.z * inv * wv.z * (gv.z / (1.f + expf(-gv.z)));
    r[3] = ov.w * inv * wv.w * (gv.w / (1.f + expf(-gv.w)));
    int col = hh * DV_ + i;
    long long b2 = (long long)tok * (2LL * VD_) + col;
#pragma unroll
    for (int j = 0; j < 4; ++j) {
        __half hb = __float2half(r[j]);
        __half lb = __float2half(r[j] - __half2float(hb));
        out2[b2 + j]       = hb;
        out2[b2 + VD_ + j] = lb;
    }
}

// ================================ launch ======================================
extern "C" void kernel_launch(void* const* d_in, const int* in_sizes, int n_in,
                              void* d_out, int out_size)
{
    const float* X    = (const float*)d_in[0];
    const int*   mod  = (const int*)  d_in[1];
    const float* Wq   = (const float*)d_in[2];
    const float* Wk   = (const float*)d_in[3];
    const float* Wv   = (const float*)d_in[4];
    const float* cq   = (const float*)d_in[5];
    const float* ck   = (const float*)d_in[6];
    const float* cv   = (const float*)d_in[7];
    const float* Wek  = (const float*)d_in[8];
    const float* Wb   = (const float*)d_in[9];
    const float* Wa   = (const float*)d_in[10];
    const float* Alog = (const float*)d_in[11];
    const float* dtb  = (const float*)d_in[12];
    const float* ow   = (const float*)d_in[13];
    const float* Wg   = (const float*)d_in[14];
    const float* onw  = (const float*)d_in[15];
    const float* Wo   = (const float*)d_in[16];
    float* out = (float*)d_out;

    float *xqkvg, *q, *v, *ke, *ba, *aa, *dec, *bm, *opre3;
    __half *X2, *Wqkvg2, *Wo2, *of2, *k2, *Wek2;
    cudaGetSymbolAddress((void**)&xqkvg, g_xqkvg);
    cudaGetSymbolAddress((void**)&q,     g_q);
    cudaGetSymbolAddress((void**)&v,     g_v);
    cudaGetSymbolAddress((void**)&ke,    g_ke);
    cudaGetSymbolAddress((void**)&ba,    g_betaA);
    cudaGetSymbolAddress((void**)&aa,    g_aA);
    cudaGetSymbolAddress((void**)&dec,   g_dec);
    cudaGetSymbolAddress((void**)&bm,    g_bm);
    cudaGetSymbolAddress((void**)&opre3, g_opre3);
    cudaGetSymbolAddress((void**)&X2,    g_X2);
    cudaGetSymbolAddress((void**)&Wqkvg2,g_Wqkvg2);
    cudaGetSymbolAddress((void**)&Wo2,   g_Wo2);
    cudaGetSymbolAddress((void**)&of2,   g_of2);
    cudaGetSymbolAddress((void**)&k2,    g_k2);
    cudaGetSymbolAddress((void**)&Wek2,  g_Wek2);

    cudaFuncSetAttribute(hmma_gemm,    cudaFuncAttributeMaxDynamicSharedMemorySize, SMEM_DYN);
    cudaFuncSetAttribute(hmma_gemm_ke, cudaFuncAttributeMaxDynamicSharedMemorySize, SMEM_DYN);
    cudaFuncSetAttribute(proj_ba_kernel, cudaFuncAttributeMaxDynamicSharedMemorySize, 8*HS_*4);

    // split fp32 -> fp16 pairs (vectorized 8-wide)
    split2_kernel<<<TOK_*HS_/2048, 256>>>(X,  X2, HS_, 1);
    split2_kernel<<<KD_*HS_/2048, 256>>>(Wq, Wqkvg2,                                 HS_, 0);
    split2_kernel<<<KD_*HS_/2048, 256>>>(Wk, Wqkvg2 + (long long)KD_*2*HS_,          HS_, 0);
    split2_kernel<<<VD_*HS_/2048, 256>>>(Wv, Wqkvg2 + (long long)(2*KD_)*2*HS_,      HS_, 0);
    split2_kernel<<<VD_*HS_/2048, 256>>>(Wg, Wqkvg2 + (long long)(2*KD_+VD_)*2*HS_,  HS_, 0);
    split2_kernel<<<HS_*VD_/2048, 256>>>(Wo, Wo2, VD_, 0);
    split2_kernel<<<E_*NH_*HD_*HD_/2048, 256>>>(Wek, Wek2, HD_, 0);

    // merged projection GEMM: [q|k|v|g] (K2 = 2*HS = 4096, N = 12288)
    hmma_gemm<<<dim3(QKVG_/128, TOK_/128), 256, SMEM_DYN>>>(X2, Wqkvg2, xqkvg, 2*HS_, QKVG_);
    proj_ba_kernel<<<TOK_/8, 256, 8*HS_*4>>>(X, Wb, Wa, ba, aa);

    // fused conv+silu+l2norm for q,k (writes q fp32 + k2 split-fp16 directly)
    fused_qk_kernel<<<TOK_, 256>>>(xqkvg, cq, ck, q, k2);

    // conv + SiLU for v
    conv_silu_kernel<<<dim3(VD_/256, L_/64, B_), 256>>>(xqkvg + 2*KD_,  cv, v, QKVG_, VD_);

    // per-expert per-head key transform on HMMA (batched over e,h; K2 = 512)
    hmma_gemm_ke<<<dim3(HD_/128, TOK_/128, E_*NH_), 256, SMEM_DYN>>>(k2, Wek2, ke);

    // gating scalars
    gating_kernel<<<(E_*B_*NH_*L_ + 255)/256, 256>>>(ba, aa, mod, Alog, dtb, dec, bm);

    // the sequential scan (scalar state, direct per-expert stores)
    scan_kernel<<<E_*B_*NH_*NV_, 128>>>(q, ke, v, dec, bm, ow, opre3);

    // RMSNorm + swish gate over summed experts -> split-fp16 A operand
    norm_gate_kernel<<<TOK_*NH_, 128>>>(opre3, xqkvg, onw, of2);

    // output projection (K2 = 2*VD = 8192)
    hmma_gemm<<<dim3(HS_/128, TOK_/128), 256, SMEM_DYN>>>(of2, Wo2, out, 2*VD_, HS_);
}